// round 7
// baseline (speedup 1.0000x reference)
#include <cuda_runtime.h>
#include <cstdint>

#define NN 100000
#define EMAX 3200000

// ---------------- scratch (device globals; no allocation allowed) ----------
__device__ int   g_is64;
__device__ int   g_indeg[NN];
__device__ float g_dinv[NN];
__device__ int   g_off[NN + 1];
__device__ int   g_cur[NN];
__device__ int   g_bsums[256];
__device__ int   g_csr[EMAX];
__device__ float g_h1[(size_t)NN * 128];   // (x@W1)*dinv
__device__ float g_a1[(size_t)NN * 128];   // layer-1 output
__device__ float g_h2[(size_t)NN * 64];    // (a1@W2)*dinv

// ---------------- dtype detection -----------------------------------------
__global__ void k_detect(const void* eidx) {
    if (threadIdx.x == 0) {
        const long long* p = (const long long*)eidx;
        int ok = 1;
        #pragma unroll 8
        for (int i = 0; i < 64; i++) {
            long long v = p[i];
            if (v < 0 || v >= NN) ok = 0;
        }
        g_is64 = ok;
    }
}

// ---------------- degree / dinv --------------------------------------------
__global__ void k_zero() {
    int i = blockIdx.x * blockDim.x + threadIdx.x;
    if (i < NN) g_indeg[i] = 0;
}

__global__ void k_count(const void* eidx, long long E) {
    long long i = (long long)blockIdx.x * blockDim.x + threadIdx.x;
    if (i >= E) return;
    int d;
    if (g_is64) d = (int)((const long long*)eidx)[E + i];
    else        d = ((const int*)eidx)[E + i];
    atomicAdd(&g_indeg[d], 1);
}

__global__ void k_dinv() {
    int i = blockIdx.x * blockDim.x + threadIdx.x;
    if (i < NN) g_dinv[i] = rsqrtf((float)(g_indeg[i] + 1));
}

// ---------------- exclusive scan (3 kernels) --------------------------------
__global__ void k_scan1() {
    __shared__ int s[512];
    int i = blockIdx.x * 512 + threadIdx.x;
    int v = (i < NN) ? g_indeg[i] : 0;
    s[threadIdx.x] = v;
    __syncthreads();
    for (int d = 1; d < 512; d <<= 1) {
        int t = 0;
        if (threadIdx.x >= d) t = s[threadIdx.x - d];
        __syncthreads();
        if (threadIdx.x >= d) s[threadIdx.x] += t;
        __syncthreads();
    }
    if (i <= NN) g_off[i] = s[threadIdx.x] - v;   // exclusive partial
    if (threadIdx.x == 511) g_bsums[blockIdx.x] = s[511];
}

__global__ void k_scan2(int nb) {
    __shared__ int s[256];
    int v = (threadIdx.x < nb) ? g_bsums[threadIdx.x] : 0;
    s[threadIdx.x] = v;
    __syncthreads();
    for (int d = 1; d < 256; d <<= 1) {
        int t = 0;
        if (threadIdx.x >= d) t = s[threadIdx.x - d];
        __syncthreads();
        if (threadIdx.x >= d) s[threadIdx.x] += t;
        __syncthreads();
    }
    if (threadIdx.x < nb) g_bsums[threadIdx.x] = s[threadIdx.x] - v;  // exclusive
}

__global__ void k_scan3() {
    int i = blockIdx.x * 512 + threadIdx.x;
    if (i <= NN) {
        int o = g_off[i] + g_bsums[blockIdx.x];
        g_off[i] = o;
        if (i < NN) g_cur[i] = o;
    }
}

// ---------------- CSR fill --------------------------------------------------
__global__ void k_fill(const void* eidx, long long E) {
    long long i = (long long)blockIdx.x * blockDim.x + threadIdx.x;
    if (i >= E) return;
    int s, d;
    if (g_is64) {
        s = (int)((const long long*)eidx)[i];
        d = (int)((const long long*)eidx)[E + i];
    } else {
        s = ((const int*)eidx)[i];
        d = ((const int*)eidx)[E + i];
    }
    int pos = atomicAdd(&g_cur[d], 1);
    g_csr[pos] = s;
}

// ---------------- GEMM with dinv-scaled epilogue ----------------------------
// out[r][c] = dinv[r] * sum_k X[r][k]*W[k][c];  X is [n,128], W is [128,OUTC]
template <int OUTC>
__global__ void __launch_bounds__(256) k_gemm_scale(
    const float* __restrict__ X, const float* __restrict__ W,
    float* __restrict__ out, int n)
{
    constexpr int KT = 32, ROWS = 64;
    constexpr int CG  = OUTC / 4;        // column groups (float4)
    constexpr int RG  = 256 / CG;        // row groups
    constexpr int RPT = ROWS / RG;       // rows per thread
    constexpr int XSTRIDE = 36;          // padded row stride (floats, 16B aligned)

    __shared__ float Xs[ROWS * XSTRIDE];
    __shared__ float Ws[KT * OUTC];

    int tid = threadIdx.x;
    int tx = tid % CG;
    int ty = tid / CG;
    int row0 = blockIdx.x * ROWS;

    float acc[RPT][4];
    #pragma unroll
    for (int r = 0; r < RPT; r++)
        #pragma unroll
        for (int j = 0; j < 4; j++) acc[r][j] = 0.f;

    for (int k0 = 0; k0 < 128; k0 += KT) {
        // load X tile: 64x32 floats = 512 float4, 2 per thread
        #pragma unroll
        for (int it = 0; it < 2; it++) {
            int idx = tid + it * 256;
            int r = idx >> 3, f = idx & 7;
            float4 v = make_float4(0.f, 0.f, 0.f, 0.f);
            int gr = row0 + r;
            if (gr < n) v = *(const float4*)&X[(size_t)gr * 128 + k0 + f * 4];
            *(float4*)&Xs[r * XSTRIDE + f * 4] = v;
        }
        // load W tile: KT x OUTC
        constexpr int WF4 = KT * OUTC / 4 / 256;
        #pragma unroll
        for (int it = 0; it < WF4; it++) {
            int idx = tid + it * 256;
            int kk = idx / (OUTC / 4), c4 = idx % (OUTC / 4);
            float4 v = *(const float4*)&W[(size_t)(k0 + kk) * OUTC + c4 * 4];
            *(float4*)&Ws[kk * OUTC + c4 * 4] = v;
        }
        __syncthreads();

        #pragma unroll
        for (int kk = 0; kk < KT; kk++) {
            float4 w = *(const float4*)&Ws[kk * OUTC + tx * 4];
            #pragma unroll
            for (int r = 0; r < RPT; r++) {
                float xv = Xs[(ty * RPT + r) * XSTRIDE + kk];
                acc[r][0] += xv * w.x;
                acc[r][1] += xv * w.y;
                acc[r][2] += xv * w.z;
                acc[r][3] += xv * w.w;
            }
        }
        __syncthreads();
    }

    #pragma unroll
    for (int r = 0; r < RPT; r++) {
        int gr = row0 + ty * RPT + r;
        if (gr < n) {
            float dv = g_dinv[gr];
            float4 o = make_float4(acc[r][0] * dv, acc[r][1] * dv,
                                   acc[r][2] * dv, acc[r][3] * dv);
            *(float4*)&out[(size_t)gr * OUTC + tx * 4] = o;
        }
    }
}

// ---------------- aggregation: warp per node --------------------------------
// out[v] = dinv[v] * (hp[v] + sum_{e: dst=v} hp[src[e]]) + bias
__global__ void __launch_bounds__(256) k_agg128(
    const float* __restrict__ hp, float* __restrict__ out,
    const float* __restrict__ bias, int n)
{
    int w = (blockIdx.x * blockDim.x + threadIdx.x) >> 5;
    if (w >= n) return;
    int lane = threadIdx.x & 31;
    const float4* h4 = (const float4*)hp;

    float4 a = h4[(size_t)w * 32 + lane];       // self loop
    int s = g_off[w], e = g_off[w + 1];
    int i = s;
    for (; i + 1 < e; i += 2) {
        int s0 = __ldg(&g_csr[i]);
        int s1 = __ldg(&g_csr[i + 1]);
        float4 m0 = h4[(size_t)s0 * 32 + lane];
        float4 m1 = h4[(size_t)s1 * 32 + lane];
        a.x += m0.x + m1.x; a.y += m0.y + m1.y;
        a.z += m0.z + m1.z; a.w += m0.w + m1.w;
    }
    if (i < e) {
        int s0 = __ldg(&g_csr[i]);
        float4 m0 = h4[(size_t)s0 * 32 + lane];
        a.x += m0.x; a.y += m0.y; a.z += m0.z; a.w += m0.w;
    }
    float dv = g_dinv[w];
    float4 b = ((const float4*)bias)[lane];
    float4 o = make_float4(a.x * dv + b.x, a.y * dv + b.y,
                           a.z * dv + b.z, a.w * dv + b.w);
    ((float4*)out)[(size_t)w * 32 + lane] = o;
}

__global__ void __launch_bounds__(256) k_agg64(
    const float* __restrict__ hp, float* __restrict__ out,
    const float* __restrict__ bias, int n)
{
    int w = (blockIdx.x * blockDim.x + threadIdx.x) >> 5;
    if (w >= n) return;
    int lane = threadIdx.x & 31;
    const float2* h2 = (const float2*)hp;

    float2 a = h2[(size_t)w * 32 + lane];
    int s = g_off[w], e = g_off[w + 1];
    int i = s;
    for (; i + 1 < e; i += 2) {
        int s0 = __ldg(&g_csr[i]);
        int s1 = __ldg(&g_csr[i + 1]);
        float2 m0 = h2[(size_t)s0 * 32 + lane];
        float2 m1 = h2[(size_t)s1 * 32 + lane];
        a.x += m0.x + m1.x; a.y += m0.y + m1.y;
    }
    if (i < e) {
        int s0 = __ldg(&g_csr[i]);
        float2 m0 = h2[(size_t)s0 * 32 + lane];
        a.x += m0.x; a.y += m0.y;
    }
    float dv = g_dinv[w];
    float2 b = ((const float2*)bias)[lane];
    float2 o = make_float2(a.x * dv + b.x, a.y * dv + b.y);
    ((float2*)out)[(size_t)w * 32 + lane] = o;
}

// ---------------- launch -----------------------------------------------------
extern "C" void kernel_launch(void* const* d_in, const int* in_sizes, int n_in,
                              void* d_out, int out_size)
{
    const float* x  = (const float*)d_in[0];
    const void*  ei = d_in[1];
    const float* W1 = (const float*)d_in[2];
    const float* b1 = (const float*)d_in[3];
    const float* W2 = (const float*)d_in[4];
    const float* b2 = (const float*)d_in[5];
    long long E = (long long)in_sizes[1] / 2;

    void *h1p, *a1p, *h2p;
    cudaGetSymbolAddress(&h1p, g_h1);
    cudaGetSymbolAddress(&a1p, g_a1);
    cudaGetSymbolAddress(&h2p, g_h2);
    float* h1 = (float*)h1p;
    float* a1 = (float*)a1p;
    float* h2 = (float*)h2p;
    float* out = (float*)d_out;

    int nblkN = (NN + 255) / 256;
    int nblkE = (int)((E + 255) / 256);
    int scanBlks = (NN + 1 + 511) / 512;       // 196

    k_detect<<<1, 32>>>(ei);
    k_zero<<<nblkN, 256>>>();
    k_count<<<nblkE, 256>>>(ei, E);
    k_dinv<<<nblkN, 256>>>();
    k_scan1<<<scanBlks, 512>>>();
    k_scan2<<<1, 256>>>(scanBlks);
    k_scan3<<<scanBlks, 512>>>();
    k_fill<<<nblkE, 256>>>(ei, E);

    int gemmBlks = (NN + 63) / 64;
    int aggBlks  = (NN + 7) / 8;               // 8 warps per 256-thread block

    // layer 1
    k_gemm_scale<128><<<gemmBlks, 256>>>(x, W1, h1, NN);
    k_agg128<<<aggBlks, 256>>>(h1, a1, b1, NN);

    // layer 2
    k_gemm_scale<64><<<gemmBlks, 256>>>(a1, W2, h2, NN);
    k_agg64<<<aggBlks, 256>>>(h2, out, b2, NN);
}

// round 9
// speedup vs baseline: 1.3351x; 1.3351x over previous
#include <cuda_runtime.h>
#include <cstdint>

#define NN 100000
#define EMAX 3200000

// ---------------- scratch (device globals; no allocation allowed) ----------
__device__ int   g_is64;
__device__ int   g_indeg[NN];
__device__ float g_dinv[NN];
__device__ int   g_off[NN + 1];
__device__ int   g_cur[NN];
__device__ int   g_bsums[256];
__device__ int   g_csr[EMAX];
__device__ float g_W12[128 * 64];          // W1 @ W2
__device__ float g_c2[64];                 // b1^T @ W2
__device__ float g_vvec[NN];               // (A_hat @ 1)
__device__ float g_P[(size_t)NN * 64];     // (x @ W12) * dinv
__device__ float g_S[(size_t)NN * 64];     // dinv^2 * (A+I) P

// ---------------- dtype detection -----------------------------------------
__global__ void k_detect(const void* eidx) {
    if (threadIdx.x == 0) {
        const long long* p = (const long long*)eidx;
        int ok = 1;
        #pragma unroll 8
        for (int i = 0; i < 64; i++) {
            long long v = p[i];
            if (v < 0 || v >= NN) ok = 0;
        }
        g_is64 = ok;
    }
}

// ---------------- degree / dinv --------------------------------------------
__global__ void k_zero() {
    int i = blockIdx.x * blockDim.x + threadIdx.x;
    if (i < NN) g_indeg[i] = 0;
}

__global__ void k_count(const void* eidx, long long E) {
    long long i = (long long)blockIdx.x * blockDim.x + threadIdx.x;
    if (i >= E) return;
    int d;
    if (g_is64) d = (int)((const long long*)eidx)[E + i];
    else        d = ((const int*)eidx)[E + i];
    atomicAdd(&g_indeg[d], 1);
}

__global__ void k_dinv() {
    int i = blockIdx.x * blockDim.x + threadIdx.x;
    if (i < NN) g_dinv[i] = rsqrtf((float)(g_indeg[i] + 1));
}

// ---------------- exclusive scan (3 kernels) --------------------------------
__global__ void k_scan1() {
    __shared__ int s[512];
    int i = blockIdx.x * 512 + threadIdx.x;
    int v = (i < NN) ? g_indeg[i] : 0;
    s[threadIdx.x] = v;
    __syncthreads();
    for (int d = 1; d < 512; d <<= 1) {
        int t = 0;
        if (threadIdx.x >= d) t = s[threadIdx.x - d];
        __syncthreads();
        if (threadIdx.x >= d) s[threadIdx.x] += t;
        __syncthreads();
    }
    if (i <= NN) g_off[i] = s[threadIdx.x] - v;   // exclusive partial
    if (threadIdx.x == 511) g_bsums[blockIdx.x] = s[511];
}

__global__ void k_scan2(int nb) {
    __shared__ int s[256];
    int v = (threadIdx.x < nb) ? g_bsums[threadIdx.x] : 0;
    s[threadIdx.x] = v;
    __syncthreads();
    for (int d = 1; d < 256; d <<= 1) {
        int t = 0;
        if (threadIdx.x >= d) t = s[threadIdx.x - d];
        __syncthreads();
        if (threadIdx.x >= d) s[threadIdx.x] += t;
        __syncthreads();
    }
    if (threadIdx.x < nb) g_bsums[threadIdx.x] = s[threadIdx.x] - v;  // exclusive
}

__global__ void k_scan3() {
    int i = blockIdx.x * 512 + threadIdx.x;
    if (i <= NN) {
        int o = g_off[i] + g_bsums[blockIdx.x];
        g_off[i] = o;
        if (i < NN) g_cur[i] = o;
    }
}

// ---------------- CSR fill --------------------------------------------------
__global__ void k_fill(const void* eidx, long long E) {
    long long i = (long long)blockIdx.x * blockDim.x + threadIdx.x;
    if (i >= E) return;
    int s, d;
    if (g_is64) {
        s = (int)((const long long*)eidx)[i];
        d = (int)((const long long*)eidx)[E + i];
    } else {
        s = ((const int*)eidx)[i];
        d = ((const int*)eidx)[E + i];
    }
    int pos = atomicAdd(&g_cur[d], 1);
    g_csr[pos] = s;
}

// ---------------- W12 = W1 @ W2 ; c2 = b1^T @ W2 -----------------------------
__global__ void k_w12(const float* __restrict__ W1, const float* __restrict__ W2,
                      const float* __restrict__ b1) {
    int idx = blockIdx.x * 256 + threadIdx.x;   // 32 blocks x 256 = 8192
    int k = idx >> 6, c = idx & 63;
    float acc = 0.f;
    #pragma unroll 8
    for (int j = 0; j < 128; j++)
        acc += W1[k * 128 + j] * W2[j * 64 + c];
    g_W12[k * 64 + c] = acc;
    if (blockIdx.x == 0 && threadIdx.x < 64) {
        int cc = threadIdx.x;
        float a2 = 0.f;
        #pragma unroll 8
        for (int j = 0; j < 128; j++)
            a2 += b1[j] * W2[j * 64 + cc];
        g_c2[cc] = a2;
    }
}

// ---------------- vvec[u] = dinv[u]*(dinv[u] + sum_in dinv[src]) -------------
__global__ void __launch_bounds__(256) k_vvec(int n) {
    int w = (blockIdx.x * blockDim.x + threadIdx.x) >> 5;
    if (w >= n) return;
    int lane = threadIdx.x & 31;
    int e = g_off[w + 1];
    float s = 0.f;
    for (int i = g_off[w] + lane; i < e; i += 32)
        s += g_dinv[__ldg(&g_csr[i])];
    #pragma unroll
    for (int o = 16; o; o >>= 1) s += __shfl_xor_sync(~0u, s, o);
    if (lane == 0) {
        float dv = g_dinv[w];
        g_vvec[w] = dv * (dv + s);
    }
}

// ---------------- GEMM with dinv-scaled epilogue ----------------------------
// out[r][c] = dinv[r] * sum_k X[r][k]*W[k][c];  X is [n,128], W is [128,OUTC]
template <int OUTC>
__global__ void __launch_bounds__(256) k_gemm_scale(
    const float* __restrict__ X, const float* __restrict__ W,
    float* __restrict__ out, int n)
{
    constexpr int KT = 32, ROWS = 64;
    constexpr int CG  = OUTC / 4;        // column groups (float4)
    constexpr int RG  = 256 / CG;        // row groups
    constexpr int RPT = ROWS / RG;       // rows per thread
    constexpr int XSTRIDE = 36;          // padded row stride

    __shared__ float Xs[ROWS * XSTRIDE];
    __shared__ float Ws[KT * OUTC];

    int tid = threadIdx.x;
    int tx = tid % CG;
    int ty = tid / CG;
    int row0 = blockIdx.x * ROWS;

    float acc[RPT][4];
    #pragma unroll
    for (int r = 0; r < RPT; r++)
        #pragma unroll
        for (int j = 0; j < 4; j++) acc[r][j] = 0.f;

    for (int k0 = 0; k0 < 128; k0 += KT) {
        #pragma unroll
        for (int it = 0; it < 2; it++) {
            int idx = tid + it * 256;
            int r = idx >> 3, f = idx & 7;
            float4 v = make_float4(0.f, 0.f, 0.f, 0.f);
            int gr = row0 + r;
            if (gr < n) v = *(const float4*)&X[(size_t)gr * 128 + k0 + f * 4];
            *(float4*)&Xs[r * XSTRIDE + f * 4] = v;
        }
        constexpr int WF4 = KT * OUTC / 4 / 256;
        #pragma unroll
        for (int it = 0; it < WF4; it++) {
            int idx = tid + it * 256;
            int kk = idx / (OUTC / 4), c4 = idx % (OUTC / 4);
            float4 v = *(const float4*)&W[(size_t)(k0 + kk) * OUTC + c4 * 4];
            *(float4*)&Ws[kk * OUTC + c4 * 4] = v;
        }
        __syncthreads();

        #pragma unroll
        for (int kk = 0; kk < KT; kk++) {
            float4 w = *(const float4*)&Ws[kk * OUTC + tx * 4];
            #pragma unroll
            for (int r = 0; r < RPT; r++) {
                float xv = Xs[(ty * RPT + r) * XSTRIDE + kk];
                acc[r][0] += xv * w.x;
                acc[r][1] += xv * w.y;
                acc[r][2] += xv * w.z;
                acc[r][3] += xv * w.w;
            }
        }
        __syncthreads();
    }

    #pragma unroll
    for (int r = 0; r < RPT; r++) {
        int gr = row0 + ty * RPT + r;
        if (gr < n) {
            float dv = g_dinv[gr];
            float4 o = make_float4(acc[r][0] * dv, acc[r][1] * dv,
                                   acc[r][2] * dv, acc[r][3] * dv);
            *(float4*)&out[(size_t)gr * OUTC + tx * 4] = o;
        }
    }
}

// ---------------- aggregation (64-wide, float2 per lane) --------------------
// S[v] = dinv[v]^2 * (P[v] + sum_{src->v} P[src])
__global__ void __launch_bounds__(256) k_agg1(
    const float* __restrict__ P, float* __restrict__ S, int n)
{
    int w = (blockIdx.x * blockDim.x + threadIdx.x) >> 5;
    if (w >= n) return;
    int lane = threadIdx.x & 31;
    const float2* p2 = (const float2*)P;

    float2 a = p2[(size_t)w * 32 + lane];       // self loop
    int i = g_off[w], e = g_off[w + 1];
    for (; i + 3 < e; i += 4) {
        int s0 = __ldg(&g_csr[i]);
        int s1 = __ldg(&g_csr[i + 1]);
        int s2 = __ldg(&g_csr[i + 2]);
        int s3 = __ldg(&g_csr[i + 3]);
        float2 m0 = p2[(size_t)s0 * 32 + lane];
        float2 m1 = p2[(size_t)s1 * 32 + lane];
        float2 m2 = p2[(size_t)s2 * 32 + lane];
        float2 m3 = p2[(size_t)s3 * 32 + lane];
        a.x += (m0.x + m1.x) + (m2.x + m3.x);
        a.y += (m0.y + m1.y) + (m2.y + m3.y);
    }
    for (; i < e; i++) {
        int s0 = __ldg(&g_csr[i]);
        float2 m0 = p2[(size_t)s0 * 32 + lane];
        a.x += m0.x; a.y += m0.y;
    }
    float dv = g_dinv[w];
    float sc = dv * dv;
    ((float2*)S)[(size_t)w * 32 + lane] = make_float2(a.x * sc, a.y * sc);
}

// out[v] = dinv[v] * (S[v] + sum S[src]) + vvec[v]*c2 + b2
__global__ void __launch_bounds__(256) k_agg2(
    const float* __restrict__ S, float* __restrict__ out,
    const float* __restrict__ b2, int n)
{
    int w = (blockIdx.x * blockDim.x + threadIdx.x) >> 5;
    if (w >= n) return;
    int lane = threadIdx.x & 31;
    const float2* s2p = (const float2*)S;

    float2 a = s2p[(size_t)w * 32 + lane];
    int i = g_off[w], e = g_off[w + 1];
    for (; i + 3 < e; i += 4) {
        int s0 = __ldg(&g_csr[i]);
        int s1 = __ldg(&g_csr[i + 1]);
        int s2 = __ldg(&g_csr[i + 2]);
        int s3 = __ldg(&g_csr[i + 3]);
        float2 m0 = s2p[(size_t)s0 * 32 + lane];
        float2 m1 = s2p[(size_t)s1 * 32 + lane];
        float2 m2 = s2p[(size_t)s2 * 32 + lane];
        float2 m3 = s2p[(size_t)s3 * 32 + lane];
        a.x += (m0.x + m1.x) + (m2.x + m3.x);
        a.y += (m0.y + m1.y) + (m2.y + m3.y);
    }
    for (; i < e; i++) {
        int s0 = __ldg(&g_csr[i]);
        float2 m0 = s2p[(size_t)s0 * 32 + lane];
        a.x += m0.x; a.y += m0.y;
    }
    float dv = g_dinv[w];
    float vv = g_vvec[w];
    float2 c2 = ((const float2*)g_c2)[lane];
    float2 b  = ((const float2*)b2)[lane];
    float2 o = make_float2(a.x * dv + vv * c2.x + b.x,
                           a.y * dv + vv * c2.y + b.y);
    ((float2*)out)[(size_t)w * 32 + lane] = o;
}

// ---------------- launch -----------------------------------------------------
extern "C" void kernel_launch(void* const* d_in, const int* in_sizes, int n_in,
                              void* d_out, int out_size)
{
    const float* x  = (const float*)d_in[0];
    const void*  ei = d_in[1];
    const float* W1 = (const float*)d_in[2];
    const float* b1 = (const float*)d_in[3];
    const float* W2 = (const float*)d_in[4];
    const float* b2 = (const float*)d_in[5];
    long long E = (long long)in_sizes[1] / 2;

    void *Pp, *Sp;
    cudaGetSymbolAddress(&Pp, g_P);
    cudaGetSymbolAddress(&Sp, g_S);
    float* P = (float*)Pp;
    float* S = (float*)Sp;
    float* out = (float*)d_out;

    int nblkN = (NN + 255) / 256;
    int nblkE = (int)((E + 255) / 256);
    int scanBlks = (NN + 1 + 511) / 512;       // 196

    // ---- graph preprocessing ----
    k_detect<<<1, 32>>>(ei);
    k_zero<<<nblkN, 256>>>();
    k_count<<<nblkE, 256>>>(ei, E);
    k_dinv<<<nblkN, 256>>>();
    k_scan1<<<scanBlks, 512>>>();
    k_scan2<<<1, 256>>>(scanBlks);
    k_scan3<<<scanBlks, 512>>>();
    k_fill<<<nblkE, 256>>>(ei, E);

    // ---- fused weights + rank-1 bias pieces ----
    const float* dW1 = W1;
    k_w12<<<32, 256>>>(dW1, W2, b1);

    int aggBlks  = (NN + 7) / 8;               // 8 warps / 256-thread block
    k_vvec<<<aggBlks, 256>>>(NN);

    // ---- single fused GEMM: P = dinv * (X @ (W1 W2)) ----
    void* W12p; cudaGetSymbolAddress(&W12p, g_W12);
    int gemmBlks = (NN + 63) / 64;
    k_gemm_scale<64><<<gemmBlks, 256>>>(x, (const float*)W12p, P, NN);

    // ---- two aggregations on 64-wide features ----
    k_agg1<<<aggBlks, 256>>>(P, S, NN);
    k_agg2<<<aggBlks, 256>>>(S, out, b2, NN);
}